// round 4
// baseline (speedup 1.0000x reference)
#include <cuda_runtime.h>

// Problem constants
#define T_DIM 4
#define B_DIM 16
#define N_DIM 1024
#define D_DIM 512
#define M_DIM (B_DIM * N_DIM)       // 16384
#define R_DIM (T_DIM * M_DIM)       // 65536
#define MD ((size_t)M_DIM * D_DIM)  // 8388608

// Scratch: projection outputs, then (in-place in g_Yq) the attention state S = q * cumsum(k*v)
__device__ __align__(16) float g_Yq[(size_t)R_DIM * D_DIM];
__device__ __align__(16) float g_Yk[(size_t)R_DIM * D_DIM];
__device__ __align__(16) float g_Yv[(size_t)R_DIM * D_DIM];

// ---------------- SGEMM: C[m,n] = sum_k A[m,k] * W[n,k] (+ bias[n]) ----------------
// A: Mrows x 512 row-major, W: 512 x 512 row-major (so this is A @ W^T), K = N = 512.
// 128x128 block tile, BK=8, 256 threads, 8x8 per thread.
// fp32 throughput on sm_103a: 3-reg FFMA is half-rate (rt_SMSP=2); full rate needs
// packed fma.rn.f32x2 (PTX-only pattern, per SASS_QUICKREF "FFMA2 from C++" note).
// Accumulators are packed over M-row pairs (pairs come free from the transposed
// As tile); B scalars are duplicated via mov.b64.
// Global->smem path is software-pipelined: next tile's LDG issues before the
// current tile's compute, hiding ~600cyc memory latency behind ~320 issue slots.

#define BM 128
#define BN 128
#define BK 8

#define FMA2(acc, a, b) asm("fma.rn.f32x2 %0, %1, %2, %0;" : "+l"(acc) : "l"(a), "l"(b))
#define DUP2(d, f)      asm("mov.b64 %0, {%1, %1};" : "=l"(d) : "f"(f))

__device__ __forceinline__ float2 unpk(unsigned long long u) {
    float2 r;
    asm("mov.b64 {%0, %1}, %2;" : "=f"(r.x), "=f"(r.y) : "l"(u));
    return r;
}

__global__ __launch_bounds__(256, 2)
void sgemm_bt(const float* __restrict__ A, const float* __restrict__ W,
              float* __restrict__ C, const float* __restrict__ bias)
{
    __shared__ __align__(16) float As[BK][BM];
    __shared__ __align__(16) float Bs[BK][BN];
    const int K = D_DIM;

    const int bm = blockIdx.y * BM;
    const int bn = blockIdx.x * BN;
    const int tid = threadIdx.x;
    const int tx = tid & 15;       // 0..15 -> 8 output columns each
    const int ty = tid >> 4;       // 0..15 -> 8 output rows each
    const int lr = tid >> 1;       // 0..127: tile row loaded by this thread
    const int lc = (tid & 1) * 4;  // 0 or 4: k-offset of the float4 loaded

    const float* Aload = A + (size_t)(bm + lr) * K + lc;
    const float* Wload = W + (size_t)(bn + lr) * K + lc;

    // acc[ip][j] packs output rows (ty*8 + 2*ip, ty*8 + 2*ip + 1) for column tx*8+j
    unsigned long long acc[4][8];
#pragma unroll
    for (int i = 0; i < 4; i++)
#pragma unroll
        for (int j = 0; j < 8; j++) acc[i][j] = 0ULL;  // bits of {0.f, 0.f}

    // Prologue: first tile's global loads
    float4 av = *(const float4*)(Aload);
    float4 bv = *(const float4*)(Wload);

    for (int k0 = 0; k0 < K; k0 += BK) {
        __syncthreads();  // previous tile fully consumed before overwrite
        As[lc + 0][lr] = av.x; As[lc + 1][lr] = av.y;
        As[lc + 2][lr] = av.z; As[lc + 3][lr] = av.w;
        Bs[lc + 0][lr] = bv.x; Bs[lc + 1][lr] = bv.y;
        Bs[lc + 2][lr] = bv.z; Bs[lc + 3][lr] = bv.w;
        __syncthreads();
        // Prefetch next tile while computing this one (hides LDG latency)
        if (k0 + BK < K) {
            av = *(const float4*)(Aload + k0 + BK);
            bv = *(const float4*)(Wload + k0 + BK);
        }
#pragma unroll
        for (int k = 0; k < BK; k++) {
            // row pairs straight out of LDS.128 (16B-aligned: ty*8 floats = 32B)
            const ulonglong2 a01 = *(const ulonglong2*)&As[k][ty * 8];
            const ulonglong2 a23 = *(const ulonglong2*)&As[k][ty * 8 + 4];
            const float4 b0 = *(const float4*)&Bs[k][tx * 8];
            const float4 b1 = *(const float4*)&Bs[k][tx * 8 + 4];
            unsigned long long bd[8];
            DUP2(bd[0], b0.x); DUP2(bd[1], b0.y); DUP2(bd[2], b0.z); DUP2(bd[3], b0.w);
            DUP2(bd[4], b1.x); DUP2(bd[5], b1.y); DUP2(bd[6], b1.z); DUP2(bd[7], b1.w);
#pragma unroll
            for (int j = 0; j < 8; j++) {
                FMA2(acc[0][j], a01.x, bd[j]);
                FMA2(acc[1][j], a01.y, bd[j]);
                FMA2(acc[2][j], a23.x, bd[j]);
                FMA2(acc[3][j], a23.y, bd[j]);
            }
        }
    }

    float bvals[8];
#pragma unroll
    for (int j = 0; j < 8; j++) bvals[j] = bias ? bias[bn + tx * 8 + j] : 0.0f;

#pragma unroll
    for (int ip = 0; ip < 4; ip++) {
        float lo[8], hi[8];
#pragma unroll
        for (int j = 0; j < 8; j++) {
            const float2 v = unpk(acc[ip][j]);
            lo[j] = v.x + bvals[j];
            hi[j] = v.y + bvals[j];
        }
        float* c0 = C + (size_t)(bm + ty * 8 + 2 * ip) * D_DIM + bn + tx * 8;
        float* c1 = c0 + D_DIM;
        *(float4*)(c0)     = make_float4(lo[0], lo[1], lo[2], lo[3]);
        *(float4*)(c0 + 4) = make_float4(lo[4], lo[5], lo[6], lo[7]);
        *(float4*)(c1)     = make_float4(hi[0], hi[1], hi[2], hi[3]);
        *(float4*)(c1 + 4) = make_float4(hi[4], hi[5], hi[6], hi[7]);
    }
}

// ---------------- LIF + causal linear attention (fully elementwise, T-scan) ----------------
// Forward spike is exactly the hard Heaviside (the surrogate cancels under
// stop_gradient: sg + (hard - sg) == hard). context = inclusive cumsum_t of
// k_spike * v_spike; S = q_spike * context. Reads g_Yq/g_Yk/g_Yv, writes S in
// place into g_Yq.
__global__ __launch_bounds__(256)
void lif_attn_kernel()
{
    const size_t e = (size_t)blockIdx.x * blockDim.x + threadIdx.x;  // over MD/4
    const size_t base = e * 4;

    float q[T_DIM][4], k[T_DIM][4], v[T_DIM][4], s[T_DIM][4];
#pragma unroll
    for (int t = 0; t < T_DIM; t++) {
        *(float4*)q[t] = *(const float4*)&g_Yq[(size_t)t * MD + base];
        *(float4*)k[t] = *(const float4*)&g_Yk[(size_t)t * MD + base];
        *(float4*)v[t] = *(const float4*)&g_Yv[(size_t)t * MD + base];
    }
#pragma unroll
    for (int c = 0; c < 4; c++) {
        float mq = 0.f, mk = 0.f, mv = 0.f, ctx = 0.f;
#pragma unroll
        for (int t = 0; t < T_DIM; t++) {
            mq = 0.9f * mq + q[t][c]; const float sq = (mq >= 1.0f) ? 1.0f : 0.0f; mq -= sq;
            mk = 0.9f * mk + k[t][c]; const float sk = (mk >= 1.0f) ? 1.0f : 0.0f; mk -= sk;
            mv = 0.9f * mv + v[t][c]; const float sv = (mv >= 1.0f) ? 1.0f : 0.0f; mv -= sv;
            ctx += sk * sv;          // inclusive cumsum over time
            s[t][c] = sq * ctx;
        }
    }
#pragma unroll
    for (int t = 0; t < T_DIM; t++)
        *(float4*)&g_Yq[(size_t)t * MD + base] = *(float4*)s[t];
}

// ---------------- launch ----------------
extern "C" void kernel_launch(void* const* d_in, const int* in_sizes, int n_in,
                              void* d_out, int out_size)
{
    (void)in_sizes; (void)n_in; (void)out_size;
    const float* x  = (const float*)d_in[0];  // (T,B,N,D) == (R_DIM, 512) row-major
    const float* Wq = (const float*)d_in[1];
    const float* Wk = (const float*)d_in[2];
    const float* Wv = (const float*)d_in[3];
    const float* Wp = (const float*)d_in[4];
    const float* bp = (const float*)d_in[5];
    float* out = (float*)d_out;

    void *pq, *pk, *pv;
    cudaGetSymbolAddress(&pq, g_Yq);
    cudaGetSymbolAddress(&pk, g_Yk);
    cudaGetSymbolAddress(&pv, g_Yv);

    dim3 grid(D_DIM / BN, R_DIM / BM);  // (4, 512) = 2048 CTAs
    sgemm_bt<<<grid, 256>>>(x, Wq, (float*)pq, nullptr);
    sgemm_bt<<<grid, 256>>>(x, Wk, (float*)pk, nullptr);
    sgemm_bt<<<grid, 256>>>(x, Wv, (float*)pv, nullptr);

    const int lif_threads = 256;
    const int lif_blocks = (int)((MD / 4) / lif_threads);  // 8192
    lif_attn_kernel<<<lif_blocks, lif_threads>>>();

    sgemm_bt<<<grid, 256>>>((const float*)pq, Wp, out, bp);
}

// round 7
// speedup vs baseline: 1.5049x; 1.5049x over previous
#include <cuda_runtime.h>
#include <cuda_fp16.h>
#include <cstdint>

#define T_DIM 4
#define M_DIM 16384
#define R_DIM 65536
#define D_DIM 512
#define MD ((size_t)M_DIM * D_DIM)
#define RD ((size_t)R_DIM * D_DIM)

// scratch (device globals; no allocs allowed)
__device__ __align__(16) float  g_Yq[RD];
__device__ __align__(16) float  g_Yk[RD];
__device__ __align__(16) float  g_Yv[RD];
__device__ __align__(16) __half g_X0[RD];          // x split plane 0
__device__ __align__(16) __half g_X1[RD];          // x split plane 1
__device__ __align__(16) __half g_S[RD];           // spike-attention state (exact small ints)
__device__ __align__(16) __half g_Wsp[8 * D_DIM * D_DIM];  // [mat 0..3][plane 0..1][n][k]

// ---------------- helpers ----------------
__device__ __forceinline__ uint32_t smem_u32(const void* p) {
    uint32_t a;
    asm("{ .reg .u64 t; cvta.to.shared.u64 t, %1; cvt.u32.u64 %0, t; }" : "=r"(a) : "l"(p));
    return a;
}
#define SW128(o) ((o) ^ (((o) >> 3) & 0x70))
#define CP_ASYNC16(sa, g) \
    asm volatile("cp.async.cg.shared.global [%0], [%1], 16;" :: "r"((uint32_t)(sa)), "l"(g))
#define CP_COMMIT() asm volatile("cp.async.commit_group;" ::: "memory")
#define CP_WAIT0()  asm volatile("cp.async.wait_group 0;" ::: "memory")
#define LDMX4(r0, r1, r2, r3, a)                                            \
    asm volatile("ldmatrix.sync.aligned.m8n8.x4.shared.b16 {%0,%1,%2,%3}, [%4];" \
                 : "=r"(r0), "=r"(r1), "=r"(r2), "=r"(r3) : "r"(a))
#define MMA16816(c, a, b0, b1)                                              \
    asm volatile("mma.sync.aligned.m16n8k16.row.col.f32.f16.f16.f32 "       \
                 "{%0,%1,%2,%3},{%4,%5,%6,%7},{%8,%9},{%0,%1,%2,%3};"       \
                 : "+f"((c)[0]), "+f"((c)[1]), "+f"((c)[2]), "+f"((c)[3])   \
                 : "r"((a)[0]), "r"((a)[1]), "r"((a)[2]), "r"((a)[3]),      \
                   "r"(b0), "r"(b1))

// ---------------- operand pre-split (fp32 -> 2x fp16, ~22 mantissa bits) ----------------
__global__ __launch_bounds__(256) void split_x(const float* __restrict__ x) {
    const size_t i = ((size_t)blockIdx.x * 256 + threadIdx.x) * 4;
    const float4 v = *(const float4*)(x + i);
    __half h0[4], h1[4];
    const float f[4] = {v.x, v.y, v.z, v.w};
#pragma unroll
    for (int c = 0; c < 4; c++) {
        h0[c] = __float2half_rn(f[c]);
        h1[c] = __float2half_rn(f[c] - __half2float(h0[c]));
    }
    *(uint2*)&g_X0[i] = *(uint2*)h0;
    *(uint2*)&g_X1[i] = *(uint2*)h1;
}

__global__ __launch_bounds__(256) void prep_w(const float* __restrict__ W0,
                                              const float* __restrict__ W1,
                                              const float* __restrict__ W2,
                                              const float* __restrict__ W3) {
    const int idx = blockIdx.x * 256 + threadIdx.x;   // 0 .. 4*262144-1
    const int mat = idx >> 18, rem = idx & 0x3FFFF;
    const float* W = (mat == 0) ? W0 : (mat == 1) ? W1 : (mat == 2) ? W2 : W3;
    const float v = W[rem];
    const __half h0 = __float2half_rn(v);
    const __half h1 = __float2half_rn(v - __half2float(h0));
    g_Wsp[(size_t)mat * 524288 + rem] = h0;
    g_Wsp[(size_t)mat * 524288 + 262144 + rem] = h1;
}

// ---------------- split GEMM on HMMA: C[m,n] = sum_k A[m,k] * W[n,k] (+bias) -------------
// Virtual K' = nph*512; k-tile kt selects the (A-plane, B-plane) pair:
//   nph=3 (projections): (A0,B0), (A0,B1), (A1,B0)   [x1*w1 term ~2^-24, dropped]
//   nph=2 (output):      (A0,B0), (A0,B1)            [A = S, exact in fp16]
// CTA 128x128, 8 warps of 64x32, BK=64, SW128 128B smem rows (conflict-free ldmatrix),
// cp.async 2-stage double buffer. All phases accumulate in fp32 registers.
__global__ __launch_bounds__(256, 2)
void mma_gemm(const __half* __restrict__ A0, const __half* __restrict__ A1,
              const __half* __restrict__ B0, const __half* __restrict__ B1,
              float* __restrict__ C, const float* __restrict__ bias, int nph) {
    extern __shared__ __align__(128) char sm_raw[];
    const uint32_t sb = (smem_u32(sm_raw) + 127) & ~127u;

    const int tid = threadIdx.x, l = tid & 31, wid = tid >> 5;
    const int bm = blockIdx.y * 128, bn = blockIdx.x * 128;
    const int wm = (wid >> 2) * 64, wn = (wid & 3) * 32;

    float acc[4][4][4];
#pragma unroll
    for (int f = 0; f < 4; f++)
#pragma unroll
        for (int n8 = 0; n8 < 4; n8++)
#pragma unroll
            for (int i = 0; i < 4; i++) acc[f][n8][i] = 0.f;

    const int NT = nph * 8;

    auto load_stage = [&](int kt, int s) {
        const int ph = kt >> 3, k0 = (kt & 7) * 64;
        const __half* Ap = (ph == 2) ? A1 : A0;
        const __half* Bp = (ph == 1) ? B1 : B0;
        const uint32_t smA = sb + s * 32768, smB = smA + 16384;
        const int r0 = tid >> 3, ch = tid & 7;    // 32 rows x 8 chunks per 256-thread pass
#pragma unroll
        for (int j = 0; j < 4; j++) {
            const int row = j * 32 + r0;
            const uint32_t dst = SW128((uint32_t)(row * 128 + ch * 16));
            CP_ASYNC16(smA + dst, Ap + (size_t)(bm + row) * D_DIM + k0 + ch * 8);
            CP_ASYNC16(smB + dst, Bp + (size_t)(bn + row) * D_DIM + k0 + ch * 8);
        }
        CP_COMMIT();
    };

    load_stage(0, 0);
    int buf = 0;
    for (int kt = 0; kt < NT; kt++) {
        CP_WAIT0();          // tile kt landed (only its group outstanding here)
        __syncthreads();     // visibility + all warps done with buffer being refilled
        if (kt + 1 < NT) load_stage(kt + 1, buf ^ 1);   // overlaps compute below
        const uint32_t smA = sb + buf * 32768, smB = smA + 16384;
#pragma unroll
        for (int s = 0; s < 4; s++) {           // 4 k16 steps per BK=64 tile
            uint32_t afr[4][4];
#pragma unroll
            for (int f = 0; f < 4; f++) {       // A frags: m16 x k16
                const int row = wm + f * 16 + (l & 15);
                const int ch = 2 * s + (l >> 4);
                LDMX4(afr[f][0], afr[f][1], afr[f][2], afr[f][3],
                      smA + SW128((uint32_t)(row * 128 + ch * 16)));
            }
            uint32_t bfr[2][4];
#pragma unroll
            for (int h = 0; h < 2; h++) {       // B frags: two n8 blocks per ldmatrix.x4
                const int row = wn + h * 16 + (l & 7) + ((l >> 4) << 3);
                const int ch = 2 * s + ((l >> 3) & 1);
                LDMX4(bfr[h][0], bfr[h][1], bfr[h][2], bfr[h][3],
                      smB + SW128((uint32_t)(row * 128 + ch * 16)));
            }
#pragma unroll
            for (int f = 0; f < 4; f++)
#pragma unroll
                for (int n8 = 0; n8 < 4; n8++)
                    MMA16816(acc[f][n8], afr[f],
                             bfr[n8 >> 1][(n8 & 1) * 2], bfr[n8 >> 1][(n8 & 1) * 2 + 1]);
        }
        buf ^= 1;
    }

    // epilogue: d0,d1 -> (row l/4, col (l%3..)*2), d2,d3 -> row+8
    const int er = l >> 2, ec = (l & 3) * 2;
#pragma unroll
    for (int f = 0; f < 4; f++) {
        const int m = bm + wm + f * 16 + er;
#pragma unroll
        for (int n8 = 0; n8 < 4; n8++) {
            const int n = bn + wn + n8 * 8 + ec;
            float b0v = 0.f, b1v = 0.f;
            if (bias) { b0v = bias[n]; b1v = bias[n + 1]; }
            *(float2*)&C[(size_t)m * D_DIM + n] =
                make_float2(acc[f][n8][0] + b0v, acc[f][n8][1] + b1v);
            *(float2*)&C[(size_t)(m + 8) * D_DIM + n] =
                make_float2(acc[f][n8][2] + b0v, acc[f][n8][3] + b1v);
        }
    }
}

// ---------------- LIF + causal linear attention with near-threshold fp32 repair ----------
// Hard Heaviside forward (surrogate cancels under stop_gradient). Split-GEMM membrane
// error is bounded ~5e-5; any membrane within EPS=2e-4 of threshold is recomputed with
// the sequential-fp32 chain that matched the reference exactly in Round 4.
#define LIF_EPS 2e-4f

__device__ __noinline__ void exact_chain(const float* __restrict__ x,
                                         const float* __restrict__ W,
                                         size_t m, int d, float* sp) {
    const float* w = W + (size_t)d * D_DIM;
    float mem = 0.f;
    for (int t = 0; t < T_DIM; t++) {
        const float* xr = x + ((size_t)t * M_DIM + m) * D_DIM;
        float a = 0.f;
        for (int kk = 0; kk < D_DIM; kk++) a = fmaf(xr[kk], w[kk], a);
        mem = 0.9f * mem + a;
        const float s = (mem >= 1.0f) ? 1.0f : 0.0f;
        sp[t] = s;
        mem -= s;
    }
}

__global__ __launch_bounds__(256) void lif_attn(const float* __restrict__ x,
                                                const float* __restrict__ Wq,
                                                const float* __restrict__ Wk,
                                                const float* __restrict__ Wv) {
    const size_t e = (size_t)blockIdx.x * blockDim.x + threadIdx.x;
    const size_t base = e * 4;
    const size_t m = base >> 9;
    const int d0 = (int)(base & 511);

    float q[T_DIM][4], k[T_DIM][4], v[T_DIM][4];
    __half s[T_DIM][4];
#pragma unroll
    for (int t = 0; t < T_DIM; t++) {
        *(float4*)q[t] = *(const float4*)&g_Yq[(size_t)t * MD + base];
        *(float4*)k[t] = *(const float4*)&g_Yk[(size_t)t * MD + base];
        *(float4*)v[t] = *(const float4*)&g_Yv[(size_t)t * MD + base];
    }
#pragma unroll
    for (int c = 0; c < 4; c++) {
        float sq[T_DIM], sk[T_DIM], sv[T_DIM];
        bool fq = false, fk = false, fv = false;
        float mq = 0.f, mk = 0.f, mv = 0.f;
#pragma unroll
        for (int t = 0; t < T_DIM; t++) {
            mq = 0.9f * mq + q[t][c]; fq |= (fabsf(mq - 1.0f) < LIF_EPS);
            float a = (mq >= 1.0f) ? 1.0f : 0.0f; sq[t] = a; mq -= a;
            mk = 0.9f * mk + k[t][c]; fk |= (fabsf(mk - 1.0f) < LIF_EPS);
            float b = (mk >= 1.0f) ? 1.0f : 0.0f; sk[t] = b; mk -= b;
            mv = 0.9f * mv + v[t][c]; fv |= (fabsf(mv - 1.0f) < LIF_EPS);
            float d = (mv >= 1.0f) ? 1.0f : 0.0f; sv[t] = d; mv -= d;
        }
        if (fq) exact_chain(x, Wq, m, d0 + c, sq);
        if (fk) exact_chain(x, Wk, m, d0 + c, sk);
        if (fv) exact_chain(x, Wv, m, d0 + c, sv);
        float ctx = 0.f;
#pragma unroll
        for (int t = 0; t < T_DIM; t++) {
            ctx += sk[t] * sv[t];
            s[t][c] = __float2half_rn(sq[t] * ctx);  // exact: small integers
        }
    }
#pragma unroll
    for (int t = 0; t < T_DIM; t++)
        *(uint2*)&g_S[(size_t)t * MD + base] = *(uint2*)s[t];
}

// ---------------- launch ----------------
extern "C" void kernel_launch(void* const* d_in, const int* in_sizes, int n_in,
                              void* d_out, int out_size) {
    (void)in_sizes; (void)n_in; (void)out_size;
    const float* x  = (const float*)d_in[0];
    const float* Wq = (const float*)d_in[1];
    const float* Wk = (const float*)d_in[2];
    const float* Wv = (const float*)d_in[3];
    const float* Wp = (const float*)d_in[4];
    const float* bp = (const float*)d_in[5];
    float* out = (float*)d_out;

    void *pq, *pk, *pv, *px0, *px1, *ps, *pw;
    cudaGetSymbolAddress(&pq, g_Yq);
    cudaGetSymbolAddress(&pk, g_Yk);
    cudaGetSymbolAddress(&pv, g_Yv);
    cudaGetSymbolAddress(&px0, g_X0);
    cudaGetSymbolAddress(&px1, g_X1);
    cudaGetSymbolAddress(&ps, g_S);
    cudaGetSymbolAddress(&pw, g_Wsp);
    const __half* X0 = (const __half*)px0;
    const __half* X1 = (const __half*)px1;
    const __half* S  = (const __half*)ps;
    const __half* wsp = (const __half*)pw;

    const int SMEM = 2 * 32768 + 128;
    cudaFuncSetAttribute(mma_gemm, cudaFuncAttributeMaxDynamicSharedMemorySize, SMEM);

    split_x<<<(int)(RD / 1024), 256>>>(x);
    prep_w<<<4096, 256>>>(Wq, Wk, Wv, Wp);

    dim3 grid(D_DIM / 128, R_DIM / 128);  // (4, 512)
    mma_gemm<<<grid, 256, SMEM>>>(X0, X1, wsp + 0 * 524288, wsp + 0 * 524288 + 262144,
                                  (float*)pq, nullptr, 3);
    mma_gemm<<<grid, 256, SMEM>>>(X0, X1, wsp + 1 * 524288, wsp + 1 * 524288 + 262144,
                                  (float*)pk, nullptr, 3);
    mma_gemm<<<grid, 256, SMEM>>>(X0, X1, wsp + 2 * 524288, wsp + 2 * 524288 + 262144,
                                  (float*)pv, nullptr, 3);

    lif_attn<<<(int)(MD / 4 / 256), 256>>>(x, Wq, Wk, Wv);

    mma_gemm<<<grid, 256, SMEM>>>(S, S, wsp + 3 * 524288, wsp + 3 * 524288 + 262144,
                                  out, bp, 2);
}

// round 9
// speedup vs baseline: 2.3048x; 1.5315x over previous
#include <cuda_runtime.h>
#include <cuda_fp16.h>
#include <cstdint>

#define T_DIM 4
#define M_DIM 16384
#define R_DIM 65536
#define D_DIM 512
#define MD ((size_t)M_DIM * D_DIM)
#define RD ((size_t)R_DIM * D_DIM)

// scratch (device globals; no allocs allowed)
__device__ __align__(16) __half  g_X0[RD];                 // fp16(x)
__device__ __align__(16) __half  g_Yq[RD];                 // projection outputs (fp16)
__device__ __align__(16) __half  g_Yk[RD];
__device__ __align__(16) __half  g_Yv[RD];
__device__ __align__(16) __half  g_S[RD];                  // spike-attention state (exact ints)
__device__ __align__(16) __half  g_Wh[4 * D_DIM * D_DIM];  // fp16 planes of Wq,Wk,Wv,Wp
__device__ __align__(4)  uint8_t g_flag[MD];               // per-(m,d) near-threshold mask

// ---------------- helpers ----------------
__device__ __forceinline__ uint32_t smem_u32(const void* p) {
    uint32_t a;
    asm("{ .reg .u64 t; cvta.to.shared.u64 t, %1; cvt.u32.u64 %0, t; }" : "=r"(a) : "l"(p));
    return a;
}
#define SW128(o) ((o) ^ (((o) >> 3) & 0x70))
#define CP_ASYNC16(sa, g) \
    asm volatile("cp.async.cg.shared.global [%0], [%1], 16;" :: "r"((uint32_t)(sa)), "l"(g))
#define CP_COMMIT() asm volatile("cp.async.commit_group;" ::: "memory")
#define CP_WAIT0()  asm volatile("cp.async.wait_group 0;" ::: "memory")
#define LDMX4(r0, r1, r2, r3, a)                                            \
    asm volatile("ldmatrix.sync.aligned.m8n8.x4.shared.b16 {%0,%1,%2,%3}, [%4];" \
                 : "=r"(r0), "=r"(r1), "=r"(r2), "=r"(r3) : "r"(a))
#define MMA16816(c, a, b0, b1)                                              \
    asm volatile("mma.sync.aligned.m16n8k16.row.col.f32.f16.f16.f32 "       \
                 "{%0,%1,%2,%3},{%4,%5,%6,%7},{%8,%9},{%0,%1,%2,%3};"       \
                 : "+f"((c)[0]), "+f"((c)[1]), "+f"((c)[2]), "+f"((c)[3])   \
                 : "r"((a)[0]), "r"((a)[1]), "r"((a)[2]), "r"((a)[3]),      \
                   "r"(b0), "r"(b1))

// ---------------- fp32 -> fp16 pre-conversions ----------------
__global__ __launch_bounds__(256) void split_x(const float* __restrict__ x) {
    const size_t i = ((size_t)blockIdx.x * 256 + threadIdx.x) * 4;
    const float4 v = *(const float4*)(x + i);
    __half h[4] = {__float2half_rn(v.x), __float2half_rn(v.y),
                   __float2half_rn(v.z), __float2half_rn(v.w)};
    *(uint2*)&g_X0[i] = *(uint2*)h;
}

__global__ __launch_bounds__(256) void prep_w(const float* __restrict__ W0,
                                              const float* __restrict__ W1,
                                              const float* __restrict__ W2,
                                              const float* __restrict__ W3) {
    const int idx = blockIdx.x * 256 + threadIdx.x;   // 0 .. 4*262144-1
    const int mat = idx >> 18, rem = idx & 0x3FFFF;
    const float* W = (mat == 0) ? W0 : (mat == 1) ? W1 : (mat == 2) ? W2 : W3;
    g_Wh[(size_t)mat * 262144 + rem] = __float2half_rn(W[rem]);
}

// ---------------- 1-plane HMMA GEMM body (structure validated in R7/R8) -----------
// C[m,n] = sum_k A[m,k] * B[n,k] (+bias). CTA 128x128, 8 warps 64x32, BK=64,
// SW128 128B smem rows (conflict-free ldmatrix), cp.async double buffer, fp32 accum.
template <typename OT>
__device__ __forceinline__ void gemm1p_body(const __half* __restrict__ A,
                                            const __half* __restrict__ B,
                                            OT* __restrict__ C,
                                            const float* __restrict__ bias,
                                            int bm, int bn, uint32_t sb) {
    const int tid = threadIdx.x, l = tid & 31, wid = tid >> 5;
    const int wm = (wid >> 2) * 64, wn = (wid & 3) * 32;

    float acc[4][4][4];
#pragma unroll
    for (int f = 0; f < 4; f++)
#pragma unroll
        for (int n8 = 0; n8 < 4; n8++)
#pragma unroll
            for (int i = 0; i < 4; i++) acc[f][n8][i] = 0.f;

    auto load_stage = [&](int kt, int st) {
        const int k0 = kt * 64;
        const uint32_t smA = sb + st * 32768, smB = smA + 16384;
        const int r0 = tid >> 3, ch = tid & 7;   // 32 rows x 8 chunks per pass
#pragma unroll
        for (int j = 0; j < 4; j++) {
            const int row = j * 32 + r0;
            const uint32_t dst = SW128((uint32_t)(row * 128 + ch * 16));
            CP_ASYNC16(smA + dst, A + (size_t)(bm + row) * D_DIM + k0 + ch * 8);
            CP_ASYNC16(smB + dst, B + (size_t)(bn + row) * D_DIM + k0 + ch * 8);
        }
        CP_COMMIT();
    };

    load_stage(0, 0);
    int buf = 0;
    for (int kt = 0; kt < 8; kt++) {
        CP_WAIT0();
        __syncthreads();
        if (kt + 1 < 8) load_stage(kt + 1, buf ^ 1);   // overlaps compute
        const uint32_t smA = sb + buf * 32768, smB = smA + 16384;
#pragma unroll
        for (int s = 0; s < 4; s++) {
            uint32_t afr[4][4];
#pragma unroll
            for (int f = 0; f < 4; f++) {
                const int row = wm + f * 16 + (l & 15);
                const int ch = 2 * s + (l >> 4);
                LDMX4(afr[f][0], afr[f][1], afr[f][2], afr[f][3],
                      smA + SW128((uint32_t)(row * 128 + ch * 16)));
            }
            uint32_t bfr[2][4];
#pragma unroll
            for (int h = 0; h < 2; h++) {
                const int row = wn + h * 16 + (l & 7) + ((l >> 4) << 3);
                const int ch = 2 * s + ((l >> 3) & 1);
                LDMX4(bfr[h][0], bfr[h][1], bfr[h][2], bfr[h][3],
                      smB + SW128((uint32_t)(row * 128 + ch * 16)));
            }
#pragma unroll
            for (int f = 0; f < 4; f++)
#pragma unroll
                for (int n8 = 0; n8 < 4; n8++)
                    MMA16816(acc[f][n8], afr[f],
                             bfr[n8 >> 1][(n8 & 1) * 2], bfr[n8 >> 1][(n8 & 1) * 2 + 1]);
        }
        buf ^= 1;
    }

    const int er = l >> 2, ec = (l & 3) * 2;
#pragma unroll
    for (int f = 0; f < 4; f++) {
        const int m = bm + wm + f * 16 + er;
#pragma unroll
        for (int n8 = 0; n8 < 4; n8++) {
            const int n = bn + wn + n8 * 8 + ec;
            float b0v = 0.f, b1v = 0.f;
            if (bias) { b0v = bias[n]; b1v = bias[n + 1]; }
            if constexpr (sizeof(OT) == 2) {
                *(__half2*)&C[(size_t)m * D_DIM + n] =
                    __floats2half2_rn(acc[f][n8][0] + b0v, acc[f][n8][1] + b1v);
                *(__half2*)&C[(size_t)(m + 8) * D_DIM + n] =
                    __floats2half2_rn(acc[f][n8][2] + b0v, acc[f][n8][3] + b1v);
            } else {
                *(float2*)&C[(size_t)m * D_DIM + n] =
                    make_float2(acc[f][n8][0] + b0v, acc[f][n8][1] + b1v);
                *(float2*)&C[(size_t)(m + 8) * D_DIM + n] =
                    make_float2(acc[f][n8][2] + b0v, acc[f][n8][3] + b1v);
            }
        }
    }
}

// Fused Q/K/V projections: grid (12, 512); the 12 bx-blocks of one by share the A tile.
__global__ __launch_bounds__(256, 2) void proj_gemm() {
    extern __shared__ __align__(128) char sm_raw[];
    const uint32_t sb = (smem_u32(sm_raw) + 127) & ~127u;
    const int mat = blockIdx.x >> 2;
    const int bn = (blockIdx.x & 3) * 128;
    const int bm = blockIdx.y * 128;
    __half* C = (mat == 0) ? g_Yq : (mat == 1) ? g_Yk : g_Yv;
    gemm1p_body<__half>(g_X0, g_Wh + (size_t)mat * 262144, C, nullptr, bm, bn, sb);
}

__global__ __launch_bounds__(256, 2) void out_gemm(float* __restrict__ out,
                                                   const float* __restrict__ bias) {
    extern __shared__ __align__(128) char sm_raw[];
    const uint32_t sb = (smem_u32(sm_raw) + 127) & ~127u;
    gemm1p_body<float>(g_S, g_Wh + (size_t)3 * 262144, out,
                       bias, blockIdx.y * 128, blockIdx.x * 128, sb);
}

// ---------------- LIF provisional pass ----------------
// Hard Heaviside forward (surrogate cancels under stop_gradient). Membrane error of the
// 1-phase fp16 GEMM + fp16 Y storage: sigma ~5e-4 (calibrated via R8's failure at
// EPS=1e-3 ~ 3.3 sigma -> ~1 flip). EPS=5e-3 ~ 10 sigma: near-threshold (m,d) elements
// get flagged (unconditional mask store, no atomics) and exactly re-resolved by the
// repair kernel before the output GEMM.
#define LIF_EPS 5e-3f

// shared provisional-spike arithmetic (must be bit-identical between lif and repair)
__device__ __forceinline__ void prov_step(float& mem, float y, float& spike) {
    mem = fmaf(0.9f, mem, y);
    spike = (mem >= 1.0f) ? 1.0f : 0.0f;
    mem -= spike;
}

__global__ __launch_bounds__(256) void lif_attn() {
    const size_t base = ((size_t)blockIdx.x * 256 + threadIdx.x) * 4;

    __half q[T_DIM][4], k[T_DIM][4], v[T_DIM][4], s[T_DIM][4];
#pragma unroll
    for (int t = 0; t < T_DIM; t++) {
        *(uint2*)q[t] = *(const uint2*)&g_Yq[(size_t)t * MD + base];
        *(uint2*)k[t] = *(const uint2*)&g_Yk[(size_t)t * MD + base];
        *(uint2*)v[t] = *(const uint2*)&g_Yv[(size_t)t * MD + base];
    }
    uint32_t flags = 0;
#pragma unroll
    for (int c = 0; c < 4; c++) {
        float sq[T_DIM], sk[T_DIM], sv[T_DIM];
        uint32_t mk = 0;
        float mq = 0.f, mkm = 0.f, mv = 0.f;
#pragma unroll
        for (int t = 0; t < T_DIM; t++) {
            mq = fmaf(0.9f, mq, __half2float(q[t][c]));
            if (fabsf(mq - 1.0f) < LIF_EPS) mk |= 1u;
            sq[t] = (mq >= 1.0f) ? 1.0f : 0.0f; mq -= sq[t];
            mkm = fmaf(0.9f, mkm, __half2float(k[t][c]));
            if (fabsf(mkm - 1.0f) < LIF_EPS) mk |= 2u;
            sk[t] = (mkm >= 1.0f) ? 1.0f : 0.0f; mkm -= sk[t];
            mv = fmaf(0.9f, mv, __half2float(v[t][c]));
            if (fabsf(mv - 1.0f) < LIF_EPS) mk |= 4u;
            sv[t] = (mv >= 1.0f) ? 1.0f : 0.0f; mv -= sv[t];
        }
        flags |= mk << (8 * c);
        float ctx = 0.f;
#pragma unroll
        for (int t = 0; t < T_DIM; t++) {
            ctx += sk[t] * sv[t];
            s[t][c] = __float2half_rn(sq[t] * ctx);   // exact: small integers
        }
    }
    *(uint32_t*)&g_flag[base] = flags;   // mostly 0
#pragma unroll
    for (int t = 0; t < T_DIM; t++)
        *(uint2*)&g_S[(size_t)t * MD + base] = *(uint2*)s[t];
}

// ---------------- exact repair: one CTA per m, one warp per flagged (m,d) ------------
// Flagged chains are recomputed with exact fp32 dot products (x, W fp32 inputs);
// unflagged chains of the same (m,d) reuse the bit-identical provisional arithmetic.
__device__ __forceinline__ void exact_spikes_warp(const float* __restrict__ x,
                                                  const float* __restrict__ W,
                                                  int m, int d, int l, float* sp) {
    const float* w = W + (size_t)d * D_DIM;
    float mem = 0.f;
    for (int t = 0; t < T_DIM; t++) {
        const float* xr = x + ((size_t)t * M_DIM + m) * D_DIM;
        float p = 0.f;
#pragma unroll
        for (int j = 0; j < 16; j++) p = fmaf(xr[l * 16 + j], w[l * 16 + j], p);
#pragma unroll
        for (int off = 16; off > 0; off >>= 1) p += __shfl_xor_sync(0xffffffffu, p, off);
        mem = fmaf(0.9f, mem, p);
        sp[t] = (mem >= 1.0f) ? 1.0f : 0.0f;
        mem -= sp[t];
    }
}

__device__ __forceinline__ void prov_spikes(const __half* __restrict__ Y,
                                            int m, int d, float* sp) {
    float mem = 0.f;
    for (int t = 0; t < T_DIM; t++) {
        float spike;
        prov_step(mem, __half2float(Y[(size_t)t * MD + (size_t)m * D_DIM + d]), spike);
        sp[t] = spike;
    }
}

__global__ __launch_bounds__(128) void repair(const float* __restrict__ x,
                                              const float* __restrict__ Wq,
                                              const float* __restrict__ Wk,
                                              const float* __restrict__ Wv) {
    const int m = blockIdx.x;
    __shared__ uint16_t list[512];
    __shared__ int cnt;
    const int tid = threadIdx.x;
    if (tid == 0) cnt = 0;
    __syncthreads();
    for (int d = tid; d < D_DIM; d += 128) {
        const uint32_t mk = g_flag[(size_t)m * D_DIM + d];
        if (mk) { int p = atomicAdd(&cnt, 1); list[p] = (uint16_t)(d | (mk << 9)); }
    }
    __syncthreads();
    const int wid = tid >> 5, l = tid & 31;
    for (int i = wid; i < cnt; i += 4) {
        const int e = list[i], d = e & 511, mk = e >> 9;
        float sq[T_DIM], sk[T_DIM], sv[T_DIM];
        if (mk & 1) exact_spikes_warp(x, Wq, m, d, l, sq); else prov_spikes(g_Yq, m, d, sq);
        if (mk & 2) exact_spikes_warp(x, Wk, m, d, l, sk); else prov_spikes(g_Yk, m, d, sk);
        if (mk & 4) exact_spikes_warp(x, Wv, m, d, l, sv); else prov_spikes(g_Yv, m, d, sv);
        if (l == 0) {
            float ctx = 0.f;
#pragma unroll
            for (int t = 0; t < T_DIM; t++) {
                ctx += sk[t] * sv[t];
                g_S[(size_t)t * MD + (size_t)m * D_DIM + d] = __float2half_rn(sq[t] * ctx);
            }
        }
    }
}

// ---------------- launch ----------------
extern "C" void kernel_launch(void* const* d_in, const int* in_sizes, int n_in,
                              void* d_out, int out_size) {
    (void)in_sizes; (void)n_in; (void)out_size;
    const float* x  = (const float*)d_in[0];
    const float* Wq = (const float*)d_in[1];
    const float* Wk = (const float*)d_in[2];
    const float* Wv = (const float*)d_in[3];
    const float* Wp = (const float*)d_in[4];
    const float* bp = (const float*)d_in[5];
    float* out = (float*)d_out;

    const int SMEM = 2 * 32768 + 128;
    cudaFuncSetAttribute(proj_gemm, cudaFuncAttributeMaxDynamicSharedMemorySize, SMEM);
    cudaFuncSetAttribute(out_gemm,  cudaFuncAttributeMaxDynamicSharedMemorySize, SMEM);

    split_x<<<(int)(RD / 1024), 256>>>(x);
    prep_w<<<4096, 256>>>(Wq, Wk, Wv, Wp);

    proj_gemm<<<dim3(12, R_DIM / 128), 256, SMEM>>>();

    lif_attn<<<(int)(MD / 4 / 256), 256>>>();

    repair<<<M_DIM, 128>>>(x, Wq, Wk, Wv);

    out_gemm<<<dim3(4, R_DIM / 128), 256, SMEM>>>(out, bp);
}

// round 11
// speedup vs baseline: 3.6652x; 1.5903x over previous
#include <cuda_runtime.h>
#include <cuda_fp16.h>
#include <cstdint>

#define T_DIM 4
#define M_DIM 16384
#define R_DIM 65536
#define D_DIM 512
#define MD ((size_t)M_DIM * D_DIM)
#define RD ((size_t)R_DIM * D_DIM)

// scratch (device globals; no allocs allowed)
__device__ __align__(16) __half  g_X0[RD];                 // fp16(x)
__device__ __align__(16) __half  g_Yq[RD];                 // projection outputs (fp16)
__device__ __align__(16) __half  g_Yk[RD];
__device__ __align__(16) __half  g_Yv[RD];
__device__ __align__(16) __half  g_S[RD];                  // spike-attention state (exact ints)
__device__ __align__(16) __half  g_Wh[4 * D_DIM * D_DIM];  // fp16 planes of Wq,Wk,Wv,Wp
__device__ __align__(4)  uint8_t g_flag[MD];               // per-(m,d) near-threshold mask

// ---------------- helpers ----------------
__device__ __forceinline__ uint32_t smem_u32(const void* p) {
    uint32_t a;
    asm("{ .reg .u64 t; cvta.to.shared.u64 t, %1; cvt.u32.u64 %0, t; }" : "=r"(a) : "l"(p));
    return a;
}
#define SW128(o) ((o) ^ (((o) >> 3) & 0x70))
#define CP_ASYNC16(sa, g) \
    asm volatile("cp.async.cg.shared.global [%0], [%1], 16;" :: "r"((uint32_t)(sa)), "l"(g))
#define CP_COMMIT() asm volatile("cp.async.commit_group;" ::: "memory")
#define CP_WAIT1()  asm volatile("cp.async.wait_group 1;" ::: "memory")
#define CP_WAIT0()  asm volatile("cp.async.wait_group 0;" ::: "memory")
#define LDMX4(r0, r1, r2, r3, a)                                            \
    asm volatile("ldmatrix.sync.aligned.m8n8.x4.shared.b16 {%0,%1,%2,%3}, [%4];" \
                 : "=r"(r0), "=r"(r1), "=r"(r2), "=r"(r3) : "r"(a))
#define MMA16816(c, a, b0, b1)                                              \
    asm volatile("mma.sync.aligned.m16n8k16.row.col.f32.f16.f16.f32 "       \
                 "{%0,%1,%2,%3},{%4,%5,%6,%7},{%8,%9},{%0,%1,%2,%3};"       \
                 : "+f"((c)[0]), "+f"((c)[1]), "+f"((c)[2]), "+f"((c)[3])   \
                 : "r"((a)[0]), "r"((a)[1]), "r"((a)[2]), "r"((a)[3]),      \
                   "r"(b0), "r"(b1))

// ---------------- fp32 -> fp16 pre-conversions ----------------
__global__ __launch_bounds__(256) void split_x(const float* __restrict__ x) {
    const size_t i = ((size_t)blockIdx.x * 256 + threadIdx.x) * 4;
    const float4 v = *(const float4*)(x + i);
    __half h[4] = {__float2half_rn(v.x), __float2half_rn(v.y),
                   __float2half_rn(v.z), __float2half_rn(v.w)};
    *(uint2*)&g_X0[i] = *(uint2*)h;
}

__global__ __launch_bounds__(256) void prep_w(const float* __restrict__ W0,
                                              const float* __restrict__ W1,
                                              const float* __restrict__ W2,
                                              const float* __restrict__ W3) {
    const int idx = blockIdx.x * 256 + threadIdx.x;   // 0 .. 4*262144-1
    const int mat = idx >> 18, rem = idx & 0x3FFFF;
    const float* W = (mat == 0) ? W0 : (mat == 1) ? W1 : (mat == 2) ? W2 : W3;
    g_Wh[(size_t)mat * 262144 + rem] = __float2half_rn(W[rem]);
}

// ---------------- 1-plane HMMA GEMM body, 3-stage cp.async pipeline -----------
// C[m,n] = sum_k A[m,k] * B[n,k] (+bias). CTA 128x128, 8 warps 64x32, BK=64,
// SW128 128B smem rows (conflict-free ldmatrix), fp32 accum.
// 3 stages: loads issued 2 tiles ahead; wait_group 1 leaves one load in flight.
// LAST tile must wait_group 0: no younger group exists, so wait_group 1 would
// permit the needed tile itself to still be in flight (R10 race).
template <typename OT>
__device__ __forceinline__ void gemm1p_body(const __half* __restrict__ A,
                                            const __half* __restrict__ B,
                                            OT* __restrict__ C,
                                            const float* __restrict__ bias,
                                            int bm, int bn, uint32_t sb) {
    const int tid = threadIdx.x, l = tid & 31, wid = tid >> 5;
    const int wm = (wid >> 2) * 64, wn = (wid & 3) * 32;

    float acc[4][4][4];
#pragma unroll
    for (int f = 0; f < 4; f++)
#pragma unroll
        for (int n8 = 0; n8 < 4; n8++)
#pragma unroll
            for (int i = 0; i < 4; i++) acc[f][n8][i] = 0.f;

    auto load_stage = [&](int kt, int st) {
        const int k0 = kt * 64;
        const uint32_t smA = sb + st * 32768, smB = smA + 16384;
        const int r0 = tid >> 3, ch = tid & 7;   // 32 rows x 8 chunks per pass
#pragma unroll
        for (int j = 0; j < 4; j++) {
            const int row = j * 32 + r0;
            const uint32_t dst = SW128((uint32_t)(row * 128 + ch * 16));
            CP_ASYNC16(smA + dst, A + (size_t)(bm + row) * D_DIM + k0 + ch * 8);
            CP_ASYNC16(smB + dst, B + (size_t)(bn + row) * D_DIM + k0 + ch * 8);
        }
        CP_COMMIT();
    };

    load_stage(0, 0);
    load_stage(1, 1);
    for (int kt = 0; kt < 8; kt++) {
        if (kt < 7) CP_WAIT1(); else CP_WAIT0();   // tile kt landed
        __syncthreads();     // all warps done with the buffer being refilled below
        if (kt + 2 < 8) load_stage(kt + 2, (kt + 2) % 3);
        const uint32_t smA = sb + (kt % 3) * 32768, smB = smA + 16384;
#pragma unroll
        for (int s = 0; s < 4; s++) {
            uint32_t afr[4][4];
#pragma unroll
            for (int f = 0; f < 4; f++) {
                const int row = wm + f * 16 + (l & 15);
                const int ch = 2 * s + (l >> 4);
                LDMX4(afr[f][0], afr[f][1], afr[f][2], afr[f][3],
                      smA + SW128((uint32_t)(row * 128 + ch * 16)));
            }
            uint32_t bfr[2][4];
#pragma unroll
            for (int h = 0; h < 2; h++) {
                const int row = wn + h * 16 + (l & 7) + ((l >> 4) << 3);
                const int ch = 2 * s + ((l >> 3) & 1);
                LDMX4(bfr[h][0], bfr[h][1], bfr[h][2], bfr[h][3],
                      smB + SW128((uint32_t)(row * 128 + ch * 16)));
            }
#pragma unroll
            for (int f = 0; f < 4; f++)
#pragma unroll
                for (int n8 = 0; n8 < 4; n8++)
                    MMA16816(acc[f][n8], afr[f],
                             bfr[n8 >> 1][(n8 & 1) * 2], bfr[n8 >> 1][(n8 & 1) * 2 + 1]);
        }
    }

    const int er = l >> 2, ec = (l & 3) * 2;
#pragma unroll
    for (int f = 0; f < 4; f++) {
        const int m = bm + wm + f * 16 + er;
#pragma unroll
        for (int n8 = 0; n8 < 4; n8++) {
            const int n = bn + wn + n8 * 8 + ec;
            float b0v = 0.f, b1v = 0.f;
            if (bias) { b0v = bias[n]; b1v = bias[n + 1]; }
            if constexpr (sizeof(OT) == 2) {
                *(__half2*)&C[(size_t)m * D_DIM + n] =
                    __floats2half2_rn(acc[f][n8][0] + b0v, acc[f][n8][1] + b1v);
                *(__half2*)&C[(size_t)(m + 8) * D_DIM + n] =
                    __floats2half2_rn(acc[f][n8][2] + b0v, acc[f][n8][3] + b1v);
            } else {
                *(float2*)&C[(size_t)m * D_DIM + n] =
                    make_float2(acc[f][n8][0] + b0v, acc[f][n8][1] + b1v);
                *(float2*)&C[(size_t)(m + 8) * D_DIM + n] =
                    make_float2(acc[f][n8][2] + b0v, acc[f][n8][3] + b1v);
            }
        }
    }
}

// Fused Q/K/V projections: grid (12, 512); the 12 bx-blocks of one by share the A tile.
__global__ __launch_bounds__(256, 2) void proj_gemm() {
    extern __shared__ __align__(128) char sm_raw[];
    const uint32_t sb = (smem_u32(sm_raw) + 127) & ~127u;
    const int mat = blockIdx.x >> 2;
    const int bn = (blockIdx.x & 3) * 128;
    const int bm = blockIdx.y * 128;
    __half* C = (mat == 0) ? g_Yq : (mat == 1) ? g_Yk : g_Yv;
    gemm1p_body<__half>(g_X0, g_Wh + (size_t)mat * 262144, C, nullptr, bm, bn, sb);
}

__global__ __launch_bounds__(256, 2) void out_gemm(float* __restrict__ out,
                                                   const float* __restrict__ bias) {
    extern __shared__ __align__(128) char sm_raw[];
    const uint32_t sb = (smem_u32(sm_raw) + 127) & ~127u;
    gemm1p_body<float>(g_S, g_Wh + (size_t)3 * 262144, out,
                       bias, blockIdx.y * 128, blockIdx.x * 128, sb);
}

// ---------------- LIF provisional pass ----------------
// Hard Heaviside forward (surrogate cancels under stop_gradient). Membrane error of
// 1-phase fp16 GEMM + fp16 Y storage: sigma ~7e-4 (R10's failure at EPS=2.5e-3 ~ 3.5
// sigma produced the predicted O(few) flips; R9's EPS=5e-3 ~ 7 sigma passed clean).
// EPS=5e-3 is the validated zero-flip margin.
#define LIF_EPS 5e-3f

__global__ __launch_bounds__(256) void lif_attn() {
    const size_t base = ((size_t)blockIdx.x * 256 + threadIdx.x) * 4;

    __half q[T_DIM][4], k[T_DIM][4], v[T_DIM][4], s[T_DIM][4];
#pragma unroll
    for (int t = 0; t < T_DIM; t++) {
        *(uint2*)q[t] = *(const uint2*)&g_Yq[(size_t)t * MD + base];
        *(uint2*)k[t] = *(const uint2*)&g_Yk[(size_t)t * MD + base];
        *(uint2*)v[t] = *(const uint2*)&g_Yv[(size_t)t * MD + base];
    }
    uint32_t flags = 0;
#pragma unroll
    for (int c = 0; c < 4; c++) {
        float sq[T_DIM], sk[T_DIM], sv[T_DIM];
        uint32_t mk = 0;
        float mq = 0.f, mkm = 0.f, mv = 0.f;
#pragma unroll
        for (int t = 0; t < T_DIM; t++) {
            mq = fmaf(0.9f, mq, __half2float(q[t][c]));
            if (fabsf(mq - 1.0f) < LIF_EPS) mk |= 1u;
            sq[t] = (mq >= 1.0f) ? 1.0f : 0.0f; mq -= sq[t];
            mkm = fmaf(0.9f, mkm, __half2float(k[t][c]));
            if (fabsf(mkm - 1.0f) < LIF_EPS) mk |= 2u;
            sk[t] = (mkm >= 1.0f) ? 1.0f : 0.0f; mkm -= sk[t];
            mv = fmaf(0.9f, mv, __half2float(v[t][c]));
            if (fabsf(mv - 1.0f) < LIF_EPS) mk |= 4u;
            sv[t] = (mv >= 1.0f) ? 1.0f : 0.0f; mv -= sv[t];
        }
        flags |= mk << (8 * c);
        float ctx = 0.f;
#pragma unroll
        for (int t = 0; t < T_DIM; t++) {
            ctx += sk[t] * sv[t];
            s[t][c] = __float2half_rn(sq[t] * ctx);   // exact: small integers
        }
    }
    *(uint32_t*)&g_flag[base] = flags;   // mostly 0
#pragma unroll
    for (int t = 0; t < T_DIM; t++)
        *(uint2*)&g_S[(size_t)t * MD + base] = *(uint2*)s[t];
}

// ---------------- exact repair: one CTA per m, x rows staged in smem ------------
// Flagged chains are recomputed with exact fp32 dots (x from smem, W rows L2-hot);
// unflagged chains of the same (m,d) reuse the bit-identical provisional arithmetic.
__device__ __forceinline__ void exact_spikes_warp(const float* __restrict__ xs,
                                                  const float* __restrict__ W,
                                                  int d, int l, float* sp) {
    const float* w = W + (size_t)d * D_DIM;
    float wv[16];
#pragma unroll
    for (int j = 0; j < 16; j++) wv[j] = w[l * 16 + j];
    float mem = 0.f;
    for (int t = 0; t < T_DIM; t++) {
        const float* xr = xs + t * D_DIM;
        float p = 0.f;
#pragma unroll
        for (int j = 0; j < 16; j++) p = fmaf(xr[l * 16 + j], wv[j], p);
#pragma unroll
        for (int off = 16; off > 0; off >>= 1) p += __shfl_xor_sync(0xffffffffu, p, off);
        mem = fmaf(0.9f, mem, p);
        sp[t] = (mem >= 1.0f) ? 1.0f : 0.0f;
        mem -= sp[t];
    }
}

__device__ __forceinline__ void prov_spikes(const __half* __restrict__ Y,
                                            int m, int d, float* sp) {
    float mem = 0.f;
    for (int t = 0; t < T_DIM; t++) {
        mem = fmaf(0.9f, mem, __half2float(Y[(size_t)t * MD + (size_t)m * D_DIM + d]));
        sp[t] = (mem >= 1.0f) ? 1.0f : 0.0f;
        mem -= sp[t];
    }
}

__global__ __launch_bounds__(128) void repair(const float* __restrict__ x,
                                              const float* __restrict__ Wq,
                                              const float* __restrict__ Wk,
                                              const float* __restrict__ Wv) {
    const int m = blockIdx.x;
    __shared__ float xs[T_DIM * D_DIM];   // 8KB: the 4 x rows of this m
    __shared__ uint16_t list[512];
    __shared__ int cnt;
    const int tid = threadIdx.x;
    if (tid == 0) cnt = 0;
    __syncthreads();
    for (int d = tid; d < D_DIM; d += 128) {
        const uint32_t mk = g_flag[(size_t)m * D_DIM + d];
        if (mk) { int p = atomicAdd(&cnt, 1); list[p] = (uint16_t)(d | (mk << 9)); }
    }
    __syncthreads();
    if (cnt == 0) return;
    // stage x rows (coalesced float4)
    for (int i = tid; i < T_DIM * D_DIM / 4; i += 128) {
        const int t = i >> 7, o = (i & 127) * 4;
        *(float4*)&xs[t * D_DIM + o] =
            *(const float4*)(x + ((size_t)t * M_DIM + m) * D_DIM + o);
    }
    __syncthreads();
    const int wid = tid >> 5, l = tid & 31;
    for (int i = wid; i < cnt; i += 4) {
        const int e = list[i], d = e & 511, mk = e >> 9;
        float sq[T_DIM], sk[T_DIM], sv[T_DIM];
        if (mk & 1) exact_spikes_warp(xs, Wq, d, l, sq); else prov_spikes(g_Yq, m, d, sq);
        if (mk & 2) exact_spikes_warp(xs, Wk, d, l, sk); else prov_spikes(g_Yk, m, d, sk);
        if (mk & 4) exact_spikes_warp(xs, Wv, d, l, sv); else prov_spikes(g_Yv, m, d, sv);
        if (l == 0) {
            float ctx = 0.f;
#pragma unroll
            for (int t = 0; t < T_DIM; t++) {
                ctx += sk[t] * sv[t];
                g_S[(size_t)t * MD + (size_t)m * D_DIM + d] = __float2half_rn(sq[t] * ctx);
            }
        }
    }
}

// ---------------- launch ----------------
extern "C" void kernel_launch(void* const* d_in, const int* in_sizes, int n_in,
                              void* d_out, int out_size) {
    (void)in_sizes; (void)n_in; (void)out_size;
    const float* x  = (const float*)d_in[0];
    const float* Wq = (const float*)d_in[1];
    const float* Wk = (const float*)d_in[2];
    const float* Wv = (const float*)d_in[3];
    const float* Wp = (const float*)d_in[4];
    const float* bp = (const float*)d_in[5];
    float* out = (float*)d_out;

    const int SMEM = 3 * 32768 + 128;
    cudaFuncSetAttribute(proj_gemm, cudaFuncAttributeMaxDynamicSharedMemorySize, SMEM);
    cudaFuncSetAttribute(out_gemm,  cudaFuncAttributeMaxDynamicSharedMemorySize, SMEM);

    split_x<<<(int)(RD / 1024), 256>>>(x);
    prep_w<<<4096, 256>>>(Wq, Wk, Wv, Wp);

    proj_gemm<<<dim3(12, R_DIM / 128), 256, SMEM>>>();

    lif_attn<<<(int)(MD / 4 / 256), 256>>>();

    repair<<<M_DIM, 128>>>(x, Wq, Wk, Wv);

    out_gemm<<<dim3(4, R_DIM / 128), 256, SMEM>>>(out, bp);
}